// round 1
// baseline (speedup 1.0000x reference)
#include <cuda_runtime.h>

// ---------------------------------------------------------------------------
// GCNEncoder: 2-layer GCN, N=100000 nodes, E=1600000 edges.
// x = emb[types]; h1 = relu(gcnconv(x, W1, b1)); out = gcnconv(h1, W2, b2)
// gcnconv with self-loops + symmetric deg^-1/2 norm:
//   out[d] = dis[d] * ( sum_{s->d} dis[s]*(x[s]@W) + dis[d]*(x[d]@W) ) + b
// Strategy: prescale h[v] = dis[v]*(x[v]@W) in GEMM epilogue; build dst-CSR
// once; warp-per-node atomic-free gather (h fits in L2).
// ---------------------------------------------------------------------------

#define MAXN 100000
#define MAXE 1600000

__device__ int   g_cnt[MAXN];
__device__ int   g_rowptr[MAXN + 1];
__device__ int   g_wptr[MAXN];
__device__ int   g_col[MAXE];
__device__ float g_dis[MAXN];
__device__ float g_h1[(size_t)MAXN * 128];
__device__ float g_a1[(size_t)MAXN * 128];
__device__ float g_h2[(size_t)MAXN * 64];

// ---------------------------- CSR build -----------------------------------

__global__ void init_cnt_kernel(int* __restrict__ cnt, int n) {
    int i = blockIdx.x * blockDim.x + threadIdx.x;
    if (i < n) cnt[i] = 0;
}

__global__ void count_kernel(const int* __restrict__ dst, int e, int* __restrict__ cnt) {
    int i = blockIdx.x * blockDim.x + threadIdx.x;
    if (i < e) atomicAdd(&cnt[dst[i]], 1);
}

// Single-block exclusive scan over cnt[0..n): rowptr[i+1] = incl prefix,
// wptr[i] = excl prefix. 1024 threads, shuffle-based, ~3 bars per 1024 chunk.
__global__ void scan_kernel(const int* __restrict__ cnt,
                            int* __restrict__ rowptr,
                            int* __restrict__ wptr, int n) {
    __shared__ int warp_sums[32];
    __shared__ int s_carry;
    int lane = threadIdx.x & 31;
    int wid  = threadIdx.x >> 5;
    if (threadIdx.x == 0) s_carry = 0;
    __syncthreads();
    for (int base = 0; base < n; base += 1024) {
        int i = base + (int)threadIdx.x;
        int v = (i < n) ? cnt[i] : 0;
        // warp inclusive scan
        int x = v;
        #pragma unroll
        for (int off = 1; off < 32; off <<= 1) {
            int t = __shfl_up_sync(0xFFFFFFFFu, x, off);
            if (lane >= off) x += t;
        }
        if (lane == 31) warp_sums[wid] = x;
        __syncthreads();
        if (wid == 0) {
            int s = warp_sums[lane];
            #pragma unroll
            for (int off = 1; off < 32; off <<= 1) {
                int t = __shfl_up_sync(0xFFFFFFFFu, s, off);
                if (lane >= off) s += t;
            }
            warp_sums[lane] = s;
        }
        __syncthreads();
        int warp_off = (wid > 0) ? warp_sums[wid - 1] : 0;
        int incl = x + warp_off;
        int carry = s_carry;
        if (i < n) {
            rowptr[i + 1] = carry + incl;
            wptr[i]       = carry + incl - v;
        }
        __syncthreads();
        if (threadIdx.x == 1023) s_carry = carry + incl;
        __syncthreads();
    }
    if (threadIdx.x == 0) rowptr[0] = 0;
}

__global__ void dis_kernel(const int* __restrict__ cnt, float* __restrict__ dis, int n) {
    int i = blockIdx.x * blockDim.x + threadIdx.x;
    if (i < n) dis[i] = rsqrtf((float)(cnt[i] + 1));  // +1 self-loop
}

__global__ void fill_kernel(const int* __restrict__ src, const int* __restrict__ dst,
                            int e, int* __restrict__ wptr, int* __restrict__ colx) {
    int i = blockIdx.x * blockDim.x + threadIdx.x;
    if (i < e) {
        int p = atomicAdd(&wptr[dst[i]], 1);
        colx[p] = src[i];
    }
}

// ---------------------------- GEMM -----------------------------------------
// C[row] = dis[row] * (A[row] @ W), A is [n,128] (or gathered emb rows),
// W is [128,BN]. BM=64, BK=32, 256 threads, each thread 8x(BN/32) outputs.

template <int BN, bool GATHER>
__global__ __launch_bounds__(256)
void gemm_kernel(const float* __restrict__ A,
                 const int*   __restrict__ types,
                 const float* __restrict__ emb,
                 const float* __restrict__ W,
                 const float* __restrict__ dis,
                 float* __restrict__ out, int n) {
    constexpr int TN = BN / 32;
    __shared__ __align__(16) float As[32][68];   // [k][m], padded
    __shared__ __align__(16) float Bs[32][BN];   // [k][col]

    int tid = threadIdx.x;
    int tx = tid & 31;        // col group
    int ty = tid >> 5;        // row group (0..7)
    int m0 = blockIdx.x * 64;

    float acc[8][TN];
    #pragma unroll
    for (int i = 0; i < 8; i++)
        #pragma unroll
        for (int j = 0; j < TN; j++) acc[i][j] = 0.0f;

    for (int kk = 0; kk < 128; kk += 32) {
        // Load A tile: 64 rows x 32 k = 512 float4, 2 per thread.
        // fi>>3 = m, fi&7 = q (float4 within the 32-k chunk).
        #pragma unroll
        for (int r = 0; r < 2; r++) {
            int fi = tid + r * 256;
            int m = fi >> 3;
            int q = fi & 7;
            int row = m0 + m;
            float4 v = make_float4(0.f, 0.f, 0.f, 0.f);
            if (row < n) {
                const float* rp = GATHER ? (emb + (size_t)types[row] * 128)
                                         : (A + (size_t)row * 128);
                v = *(const float4*)(rp + kk + q * 4);
            }
            As[q * 4 + 0][m] = v.x;
            As[q * 4 + 1][m] = v.y;
            As[q * 4 + 2][m] = v.z;
            As[q * 4 + 3][m] = v.w;
        }
        // Load W tile: 32 x BN
        constexpr int F4 = BN / 4;
        constexpr int LOADS = (32 * F4) / 256;
        #pragma unroll
        for (int r = 0; r < LOADS; r++) {
            int fi = tid + r * 256;
            int k  = fi / F4;
            int c4 = fi % F4;
            *(float4*)&Bs[k][c4 * 4] = *(const float4*)(W + (size_t)(kk + k) * BN + c4 * 4);
        }
        __syncthreads();

        #pragma unroll
        for (int k = 0; k < 32; k++) {
            float a[8];
            float4 a0 = *(const float4*)&As[k][ty * 8];
            float4 a1 = *(const float4*)&As[k][ty * 8 + 4];
            a[0] = a0.x; a[1] = a0.y; a[2] = a0.z; a[3] = a0.w;
            a[4] = a1.x; a[5] = a1.y; a[6] = a1.z; a[7] = a1.w;
            float b[TN];
            if constexpr (TN == 4) {
                float4 bv = *(const float4*)&Bs[k][tx * 4];
                b[0] = bv.x; b[1] = bv.y; b[2] = bv.z; b[3] = bv.w;
            } else {
                float2 bv = *(const float2*)&Bs[k][tx * 2];
                b[0] = bv.x; b[1] = bv.y;
            }
            #pragma unroll
            for (int i = 0; i < 8; i++)
                #pragma unroll
                for (int j = 0; j < TN; j++)
                    acc[i][j] = fmaf(a[i], b[j], acc[i][j]);
        }
        __syncthreads();
    }

    #pragma unroll
    for (int i = 0; i < 8; i++) {
        int row = m0 + ty * 8 + i;
        if (row < n) {
            float sc = dis[row];
            if constexpr (TN == 4) {
                float4 o = make_float4(sc * acc[i][0], sc * acc[i][1],
                                       sc * acc[i][2], sc * acc[i][3]);
                *(float4*)(out + (size_t)row * BN + tx * 4) = o;
            } else {
                float2 o = make_float2(sc * acc[i][0], sc * acc[i][1]);
                *(float2*)(out + (size_t)row * BN + tx * 2) = o;
            }
        }
    }
}

// ---------------------------- Aggregation ----------------------------------
// One warp per destination node. acc = h[d] (self) + sum over CSR neighbors.
// out[d] = (relu?)(dis[d]*acc + bias)

template <int F, bool RELU>
__global__ __launch_bounds__(256)
void agg_kernel(const float* __restrict__ h,
                const int* __restrict__ rowptr,
                const int* __restrict__ colx,
                const float* __restrict__ dis,
                const float* __restrict__ bias,
                float* __restrict__ out, int n) {
    constexpr int V = F / 32;  // floats per lane
    int w = (int)((blockIdx.x * blockDim.x + threadIdx.x) >> 5);
    int lane = threadIdx.x & 31;
    if (w >= n) return;

    float acc[V];
    {
        const float* hp = h + (size_t)w * F + lane * V;
        if constexpr (V == 4) {
            float4 v = *(const float4*)hp;
            acc[0] = v.x; acc[1] = v.y; acc[2] = v.z; acc[3] = v.w;
        } else {
            float2 v = *(const float2*)hp;
            acc[0] = v.x; acc[1] = v.y;
        }
    }

    int j  = rowptr[w];
    int j1 = rowptr[w + 1];
    // unroll by 2 for MLP
    for (; j + 1 < j1; j += 2) {
        int sA = colx[j];
        int sB = colx[j + 1];
        const float* pA = h + (size_t)sA * F + lane * V;
        const float* pB = h + (size_t)sB * F + lane * V;
        if constexpr (V == 4) {
            float4 va = __ldg((const float4*)pA);
            float4 vb = __ldg((const float4*)pB);
            acc[0] += va.x + vb.x; acc[1] += va.y + vb.y;
            acc[2] += va.z + vb.z; acc[3] += va.w + vb.w;
        } else {
            float2 va = __ldg((const float2*)pA);
            float2 vb = __ldg((const float2*)pB);
            acc[0] += va.x + vb.x; acc[1] += va.y + vb.y;
        }
    }
    if (j < j1) {
        int s = colx[j];
        const float* p = h + (size_t)s * F + lane * V;
        if constexpr (V == 4) {
            float4 v = __ldg((const float4*)p);
            acc[0] += v.x; acc[1] += v.y; acc[2] += v.z; acc[3] += v.w;
        } else {
            float2 v = __ldg((const float2*)p);
            acc[0] += v.x; acc[1] += v.y;
        }
    }

    float sc = dis[w];
    float res[V];
    #pragma unroll
    for (int i = 0; i < V; i++) {
        res[i] = sc * acc[i] + bias[lane * V + i];
        if constexpr (RELU) res[i] = fmaxf(res[i], 0.0f);
    }
    float* op = out + (size_t)w * F + lane * V;
    if constexpr (V == 4) {
        *(float4*)op = make_float4(res[0], res[1], res[2], res[3]);
    } else {
        *(float2*)op = make_float2(res[0], res[1]);
    }
}

// ---------------------------- Launch ----------------------------------------

extern "C" void kernel_launch(void* const* d_in, const int* in_sizes, int n_in,
                              void* d_out, int out_size) {
    const int*   types = (const int*)d_in[0];
    const int*   ei    = (const int*)d_in[1];
    const float* emb   = (const float*)d_in[2];
    const float* W1    = (const float*)d_in[3];
    const float* b1    = (const float*)d_in[4];
    const float* W2    = (const float*)d_in[5];
    const float* b2    = (const float*)d_in[6];
    float* out = (float*)d_out;

    int n = in_sizes[0];
    int e = in_sizes[1] / 2;
    if (n > MAXN) n = MAXN;
    if (e > MAXE) e = MAXE;
    const int* src = ei;
    const int* dst = ei + e;

    int *cnt, *rowptr, *wptr, *colx;
    float *dis, *h1, *a1, *h2;
    cudaGetSymbolAddress((void**)&cnt,    g_cnt);
    cudaGetSymbolAddress((void**)&rowptr, g_rowptr);
    cudaGetSymbolAddress((void**)&wptr,   g_wptr);
    cudaGetSymbolAddress((void**)&colx,   g_col);
    cudaGetSymbolAddress((void**)&dis,    g_dis);
    cudaGetSymbolAddress((void**)&h1,     g_h1);
    cudaGetSymbolAddress((void**)&a1,     g_a1);
    cudaGetSymbolAddress((void**)&h2,     g_h2);

    int nb_n = (n + 255) / 256;
    int nb_e = (e + 255) / 256;

    init_cnt_kernel<<<nb_n, 256>>>(cnt, n);
    count_kernel<<<nb_e, 256>>>(dst, e, cnt);
    scan_kernel<<<1, 1024>>>(cnt, rowptr, wptr, n);
    dis_kernel<<<nb_n, 256>>>(cnt, dis, n);
    fill_kernel<<<nb_e, 256>>>(src, dst, e, wptr, colx);

    int gemm_blocks = (n + 63) / 64;
    int agg_blocks  = (n + 7) / 8;  // 8 warps/block, warp per node

    // Layer 1: h1 = dis * (emb[types] @ W1); a1 = relu(dis*(agg h1) + b1)
    gemm_kernel<128, true><<<gemm_blocks, 256>>>(nullptr, types, emb, W1, dis, h1, n);
    agg_kernel<128, true><<<agg_blocks, 256>>>(h1, rowptr, colx, dis, b1, a1, n);

    // Layer 2: h2 = dis * (a1 @ W2); out = dis*(agg h2) + b2
    gemm_kernel<64, false><<<gemm_blocks, 256>>>(a1, nullptr, nullptr, W2, dis, h2, n);
    agg_kernel<64, false><<<agg_blocks, 256>>>(h2, rowptr, colx, dis, b2, out, n);
}

// round 2
// speedup vs baseline: 1.2836x; 1.2836x over previous
#include <cuda_runtime.h>

// ---------------------------------------------------------------------------
// GCNEncoder: 2-layer GCN, N=100000 nodes, E=1600000 edges, 1000 node types.
// Key trick: x = emb[types] => h1[v] = h_type[type[v]] where
// h_type = emb @ W1 is only [1000,128] (33 MFLOP instead of 3.3 GFLOP).
// Layer 1 aggregation gathers dis[s]*h_type[type[s]] per edge from a 512KB
// L1/L2-resident table. Layer 2 is a real per-node GEMM + gather.
// ---------------------------------------------------------------------------

#define MAXN 100000
#define MAXE 1600000
#define MAXT 4096

__device__ int   g_cnt[MAXN];
__device__ int   g_rowptr[MAXN + 1];
__device__ int   g_wptr[MAXN];
__device__ int   g_col[MAXE];
__device__ float g_dis[MAXN];
__device__ float g_ht[(size_t)MAXT * 128];     // h_type = emb @ W1
__device__ float g_a1[(size_t)MAXN * 128];     // relu layer-1 output
__device__ float g_h2[(size_t)MAXN * 64];      // dis * (a1 @ W2)

// ---------------------------- CSR build -----------------------------------

__global__ void init_cnt_kernel(int* __restrict__ cnt, int n) {
    int i = blockIdx.x * blockDim.x + threadIdx.x;
    if (i < n) cnt[i] = 0;
}

__global__ void count_kernel(const int* __restrict__ dst, int e, int* __restrict__ cnt) {
    int i = blockIdx.x * blockDim.x + threadIdx.x;
    if (i < e) atomicAdd(&cnt[dst[i]], 1);
}

// Single-block scan: rowptr[i+1]=incl prefix, wptr[i]=excl prefix.
__global__ void scan_kernel(const int* __restrict__ cnt,
                            int* __restrict__ rowptr,
                            int* __restrict__ wptr, int n) {
    __shared__ int warp_sums[32];
    __shared__ int s_carry;
    int lane = threadIdx.x & 31;
    int wid  = threadIdx.x >> 5;
    if (threadIdx.x == 0) s_carry = 0;
    __syncthreads();
    for (int base = 0; base < n; base += 1024) {
        int i = base + (int)threadIdx.x;
        int v = (i < n) ? cnt[i] : 0;
        int x = v;
        #pragma unroll
        for (int off = 1; off < 32; off <<= 1) {
            int t = __shfl_up_sync(0xFFFFFFFFu, x, off);
            if (lane >= off) x += t;
        }
        if (lane == 31) warp_sums[wid] = x;
        __syncthreads();
        if (wid == 0) {
            int s = warp_sums[lane];
            #pragma unroll
            for (int off = 1; off < 32; off <<= 1) {
                int t = __shfl_up_sync(0xFFFFFFFFu, s, off);
                if (lane >= off) s += t;
            }
            warp_sums[lane] = s;
        }
        __syncthreads();
        int warp_off = (wid > 0) ? warp_sums[wid - 1] : 0;
        int incl = x + warp_off;
        int carry = s_carry;
        if (i < n) {
            rowptr[i + 1] = carry + incl;
            wptr[i]       = carry + incl - v;
        }
        __syncthreads();
        if (threadIdx.x == 1023) s_carry = carry + incl;
        __syncthreads();
    }
    if (threadIdx.x == 0) rowptr[0] = 0;
}

__global__ void dis_kernel(const int* __restrict__ cnt, float* __restrict__ dis, int n) {
    int i = blockIdx.x * blockDim.x + threadIdx.x;
    if (i < n) dis[i] = rsqrtf((float)(cnt[i] + 1));  // +1 self-loop
}

__global__ void fill_kernel(const int* __restrict__ src, const int* __restrict__ dst,
                            int e, int* __restrict__ wptr, int* __restrict__ colx) {
    int i = blockIdx.x * blockDim.x + threadIdx.x;
    if (i < e) {
        int p = atomicAdd(&wptr[dst[i]], 1);
        colx[p] = src[i];
    }
}

// ---------------------------- Type GEMM ------------------------------------
// h_type = emb @ W1, [nt,128] x [128,128]. Tiny (nt=1000). BM=64 tile.

__global__ __launch_bounds__(256)
void gemm_type_kernel(const float* __restrict__ A,
                      const float* __restrict__ W,
                      float* __restrict__ out, int n) {
    __shared__ __align__(16) float As[32][68];
    __shared__ __align__(16) float Bs[32][128];

    int tid = threadIdx.x;
    int tx = tid & 31;
    int ty = tid >> 5;
    int m0 = blockIdx.x * 64;

    float acc[8][4];
    #pragma unroll
    for (int i = 0; i < 8; i++)
        #pragma unroll
        for (int j = 0; j < 4; j++) acc[i][j] = 0.0f;

    for (int kk = 0; kk < 128; kk += 32) {
        #pragma unroll
        for (int r = 0; r < 2; r++) {
            int fi = tid + r * 256;
            int m = fi >> 3;
            int q = fi & 7;
            int row = m0 + m;
            float4 v = make_float4(0.f, 0.f, 0.f, 0.f);
            if (row < n) v = *(const float4*)(A + (size_t)row * 128 + kk + q * 4);
            As[q * 4 + 0][m] = v.x;
            As[q * 4 + 1][m] = v.y;
            As[q * 4 + 2][m] = v.z;
            As[q * 4 + 3][m] = v.w;
        }
        #pragma unroll
        for (int r = 0; r < 4; r++) {
            int fi = tid + r * 256;
            int k  = fi >> 5;
            int c4 = fi & 31;
            *(float4*)&Bs[k][c4 * 4] = *(const float4*)(W + (size_t)(kk + k) * 128 + c4 * 4);
        }
        __syncthreads();
        #pragma unroll
        for (int k = 0; k < 32; k++) {
            float4 a0 = *(const float4*)&As[k][ty * 8];
            float4 a1 = *(const float4*)&As[k][ty * 8 + 4];
            float a[8] = {a0.x, a0.y, a0.z, a0.w, a1.x, a1.y, a1.z, a1.w};
            float4 bv = *(const float4*)&Bs[k][tx * 4];
            float b[4] = {bv.x, bv.y, bv.z, bv.w};
            #pragma unroll
            for (int i = 0; i < 8; i++)
                #pragma unroll
                for (int j = 0; j < 4; j++)
                    acc[i][j] = fmaf(a[i], b[j], acc[i][j]);
        }
        __syncthreads();
    }
    #pragma unroll
    for (int i = 0; i < 8; i++) {
        int row = m0 + ty * 8 + i;
        if (row < n)
            *(float4*)(out + (size_t)row * 128 + tx * 4) =
                make_float4(acc[i][0], acc[i][1], acc[i][2], acc[i][3]);
    }
}

// ---------------------------- Fused layer-1 aggregation ---------------------
// One warp per dst node. acc = dis[d]*ht[type[d]] + sum_s dis[s]*ht[type[s]];
// a1[d] = relu(dis[d]*acc + b1). ht is 512KB -> L1/L2 resident.

__global__ __launch_bounds__(256)
void agg1_fused_kernel(const float* __restrict__ ht,
                       const int* __restrict__ types,
                       const int* __restrict__ rowptr,
                       const int* __restrict__ colx,
                       const float* __restrict__ dis,
                       const float* __restrict__ bias,
                       float* __restrict__ out, int n) {
    int w = (int)((blockIdx.x * blockDim.x + threadIdx.x) >> 5);
    int lane = threadIdx.x & 31;
    if (w >= n) return;

    float dd = __ldg(&dis[w]);
    int   td = __ldg(&types[w]);
    float4 v0 = __ldg((const float4*)(ht + (size_t)td * 128) + lane);
    float ax = dd * v0.x, ay = dd * v0.y, az = dd * v0.z, aw = dd * v0.w;

    int j  = __ldg(&rowptr[w]);
    int j1 = __ldg(&rowptr[w + 1]);
    while (j < j1) {
        int m = j1 - j;
        if (m > 32) m = 32;
        int t = 0;
        float ds = 0.0f;
        if (lane < m) {
            int s = __ldg(&colx[j + lane]);
            t  = __ldg(&types[s]);
            ds = __ldg(&dis[s]);
        }
        int b = 0;
        for (; b + 1 < m; b += 2) {
            int   tA = __shfl_sync(0xFFFFFFFFu, t,  b);
            float dA = __shfl_sync(0xFFFFFFFFu, ds, b);
            int   tB = __shfl_sync(0xFFFFFFFFu, t,  b + 1);
            float dB = __shfl_sync(0xFFFFFFFFu, ds, b + 1);
            float4 vA = __ldg((const float4*)(ht + (size_t)tA * 128) + lane);
            float4 vB = __ldg((const float4*)(ht + (size_t)tB * 128) + lane);
            ax = fmaf(dA, vA.x, ax); ay = fmaf(dA, vA.y, ay);
            az = fmaf(dA, vA.z, az); aw = fmaf(dA, vA.w, aw);
            ax = fmaf(dB, vB.x, ax); ay = fmaf(dB, vB.y, ay);
            az = fmaf(dB, vB.z, az); aw = fmaf(dB, vB.w, aw);
        }
        if (b < m) {
            int   tA = __shfl_sync(0xFFFFFFFFu, t,  b);
            float dA = __shfl_sync(0xFFFFFFFFu, ds, b);
            float4 vA = __ldg((const float4*)(ht + (size_t)tA * 128) + lane);
            ax = fmaf(dA, vA.x, ax); ay = fmaf(dA, vA.y, ay);
            az = fmaf(dA, vA.z, az); aw = fmaf(dA, vA.w, aw);
        }
        j += m;
    }

    float4 bb = __ldg((const float4*)bias + lane);
    float4 res = make_float4(fmaxf(fmaf(dd, ax, bb.x), 0.0f),
                             fmaxf(fmaf(dd, ay, bb.y), 0.0f),
                             fmaxf(fmaf(dd, az, bb.z), 0.0f),
                             fmaxf(fmaf(dd, aw, bb.w), 0.0f));
    ((float4*)(out + (size_t)w * 128))[lane] = res;
}

// ---------------------------- Layer-2 GEMM ----------------------------------
// h2[row] = dis[row] * (a1[row] @ W2). [n,128] x [128,64].
// BM=128, BN=64, BK=32, 256 threads, 8x4 per-thread tile.

__global__ __launch_bounds__(256)
void gemm2_kernel(const float* __restrict__ A,
                  const float* __restrict__ W,
                  const float* __restrict__ dis,
                  float* __restrict__ out, int n) {
    __shared__ __align__(16) float As[32][132];
    __shared__ __align__(16) float Bs[32][64];

    int tid = threadIdx.x;
    int tx = tid & 15;        // col group (4 cols)
    int ty = tid >> 4;        // row group (8 rows)
    int m0 = blockIdx.x * 128;

    float acc[8][4];
    #pragma unroll
    for (int i = 0; i < 8; i++)
        #pragma unroll
        for (int j = 0; j < 4; j++) acc[i][j] = 0.0f;

    for (int kk = 0; kk < 128; kk += 32) {
        // A tile: 128 x 32 = 1024 float4, 4 per thread
        #pragma unroll
        for (int r = 0; r < 4; r++) {
            int fi = tid + r * 256;
            int m = fi >> 3;
            int q = fi & 7;
            int row = m0 + m;
            float4 v = make_float4(0.f, 0.f, 0.f, 0.f);
            if (row < n) v = *(const float4*)(A + (size_t)row * 128 + kk + q * 4);
            As[q * 4 + 0][m] = v.x;
            As[q * 4 + 1][m] = v.y;
            As[q * 4 + 2][m] = v.z;
            As[q * 4 + 3][m] = v.w;
        }
        // B tile: 32 x 64 = 512 float4, 2 per thread
        #pragma unroll
        for (int r = 0; r < 2; r++) {
            int fi = tid + r * 256;
            int k  = fi >> 4;
            int c4 = fi & 15;
            *(float4*)&Bs[k][c4 * 4] = *(const float4*)(W + (size_t)(kk + k) * 64 + c4 * 4);
        }
        __syncthreads();
        #pragma unroll
        for (int k = 0; k < 32; k++) {
            float4 a0 = *(const float4*)&As[k][ty * 8];
            float4 a1 = *(const float4*)&As[k][ty * 8 + 4];
            float a[8] = {a0.x, a0.y, a0.z, a0.w, a1.x, a1.y, a1.z, a1.w};
            float4 bv = *(const float4*)&Bs[k][tx * 4];
            float b[4] = {bv.x, bv.y, bv.z, bv.w};
            #pragma unroll
            for (int i = 0; i < 8; i++)
                #pragma unroll
                for (int j = 0; j < 4; j++)
                    acc[i][j] = fmaf(a[i], b[j], acc[i][j]);
        }
        __syncthreads();
    }

    #pragma unroll
    for (int i = 0; i < 8; i++) {
        int row = m0 + ty * 8 + i;
        if (row < n) {
            float sc = dis[row];
            *(float4*)(out + (size_t)row * 64 + tx * 4) =
                make_float4(sc * acc[i][0], sc * acc[i][1],
                            sc * acc[i][2], sc * acc[i][3]);
        }
    }
}

// ---------------------------- Layer-2 aggregation ---------------------------
// One warp per dst node over h2 [n,64] (25.6MB, L2-resident).

__global__ __launch_bounds__(256)
void agg2_kernel(const float* __restrict__ h,
                 const int* __restrict__ rowptr,
                 const int* __restrict__ colx,
                 const float* __restrict__ dis,
                 const float* __restrict__ bias,
                 float* __restrict__ out, int n) {
    int w = (int)((blockIdx.x * blockDim.x + threadIdx.x) >> 5);
    int lane = threadIdx.x & 31;
    if (w >= n) return;

    float2 acc;
    {
        float2 v = *(const float2*)(h + (size_t)w * 64 + lane * 2);
        acc.x = v.x; acc.y = v.y;
    }
    int j  = __ldg(&rowptr[w]);
    int j1 = __ldg(&rowptr[w + 1]);
    for (; j + 1 < j1; j += 2) {
        int sA = __ldg(&colx[j]);
        int sB = __ldg(&colx[j + 1]);
        float2 va = __ldg((const float2*)(h + (size_t)sA * 64 + lane * 2));
        float2 vb = __ldg((const float2*)(h + (size_t)sB * 64 + lane * 2));
        acc.x += va.x + vb.x;
        acc.y += va.y + vb.y;
    }
    if (j < j1) {
        int s = __ldg(&colx[j]);
        float2 v = __ldg((const float2*)(h + (size_t)s * 64 + lane * 2));
        acc.x += v.x;
        acc.y += v.y;
    }
    float sc = dis[w];
    float2 bb = *(const float2*)(bias + lane * 2);
    *(float2*)(out + (size_t)w * 64 + lane * 2) =
        make_float2(fmaf(sc, acc.x, bb.x), fmaf(sc, acc.y, bb.y));
}

// ---------------------------- Launch ----------------------------------------

extern "C" void kernel_launch(void* const* d_in, const int* in_sizes, int n_in,
                              void* d_out, int out_size) {
    const int*   types = (const int*)d_in[0];
    const int*   ei    = (const int*)d_in[1];
    const float* emb   = (const float*)d_in[2];
    const float* W1    = (const float*)d_in[3];
    const float* b1    = (const float*)d_in[4];
    const float* W2    = (const float*)d_in[5];
    const float* b2    = (const float*)d_in[6];
    float* out = (float*)d_out;

    int n  = in_sizes[0];
    int e  = in_sizes[1] / 2;
    int nt = in_sizes[2] / 128;   // number of node types
    if (n > MAXN) n = MAXN;
    if (e > MAXE) e = MAXE;
    if (nt > MAXT) nt = MAXT;
    const int* src = ei;
    const int* dst = ei + e;

    int *cnt, *rowptr, *wptr, *colx;
    float *dis, *ht, *a1, *h2;
    cudaGetSymbolAddress((void**)&cnt,    g_cnt);
    cudaGetSymbolAddress((void**)&rowptr, g_rowptr);
    cudaGetSymbolAddress((void**)&wptr,   g_wptr);
    cudaGetSymbolAddress((void**)&colx,   g_col);
    cudaGetSymbolAddress((void**)&dis,    g_dis);
    cudaGetSymbolAddress((void**)&ht,     g_ht);
    cudaGetSymbolAddress((void**)&a1,     g_a1);
    cudaGetSymbolAddress((void**)&h2,     g_h2);

    int nb_n = (n + 255) / 256;
    int nb_e = (e + 255) / 256;

    // h_type = emb @ W1 (independent of CSR build)
    gemm_type_kernel<<<(nt + 63) / 64, 256>>>(emb, W1, ht, nt);

    // CSR build
    init_cnt_kernel<<<nb_n, 256>>>(cnt, n);
    count_kernel<<<nb_e, 256>>>(dst, e, cnt);
    scan_kernel<<<1, 1024>>>(cnt, rowptr, wptr, n);
    dis_kernel<<<nb_n, 256>>>(cnt, dis, n);
    fill_kernel<<<nb_e, 256>>>(src, dst, e, wptr, colx);

    int agg_blocks = (n + 7) / 8;   // 8 warps/block

    // Layer 1: fused gather + aggregate from h_type table
    agg1_fused_kernel<<<agg_blocks, 256>>>(ht, types, rowptr, colx, dis, b1, a1, n);

    // Layer 2
    gemm2_kernel<<<(n + 127) / 128, 256>>>(a1, W2, dis, h2, n);
    agg2_kernel<<<agg_blocks, 256>>>(h2, rowptr, colx, dis, b2, out, n);
}

// round 3
// speedup vs baseline: 1.7256x; 1.3443x over previous
#include <cuda_runtime.h>

// ---------------------------------------------------------------------------
// GCNEncoder: 2-layer GCN, N=100000 nodes, E=1600000 edges, 1000 node types.
// h_type = emb @ W1 is only [1000,128]; layer-1 agg gathers dis[s]*ht[type[s]]
// from the 512KB L1/L2-resident table. Layer 2: real GEMM + gather.
// Round 3: multi-block scan (was 89us single-block), dis fused into scan,
// memset node instead of init kernel.
// ---------------------------------------------------------------------------

#define MAXN 100000
#define MAXE 1600000
#define MAXT 4096
#define SCAN_CHUNK 1024
#define MAXNB ((MAXN + SCAN_CHUNK - 1) / SCAN_CHUNK)

__device__ int   g_cnt[MAXN];
__device__ int   g_rowptr[MAXN + 1];
__device__ int   g_wptr[MAXN];
__device__ int   g_col[MAXE];
__device__ int   g_partials[MAXNB];
__device__ float g_dis[MAXN];
__device__ float g_ht[(size_t)MAXT * 128];     // h_type = emb @ W1
__device__ float g_a1[(size_t)MAXN * 128];     // relu layer-1 output
__device__ float g_h2[(size_t)MAXN * 64];      // dis * (a1 @ W2)

// ---------------------------- CSR build -----------------------------------

__global__ void count_kernel(const int* __restrict__ dst, int e, int* __restrict__ cnt) {
    int i = blockIdx.x * blockDim.x + threadIdx.x;
    if (i < e) atomicAdd(&cnt[dst[i]], 1);
}

// Per-chunk sums: block b sums cnt[b*1024 .. b*1024+1023] -> partials[b]
__global__ __launch_bounds__(256)
void blocksum_kernel(const int* __restrict__ cnt, int* __restrict__ partials, int n) {
    int base = blockIdx.x * SCAN_CHUNK;
    int sum = 0;
    #pragma unroll
    for (int r = 0; r < 4; r++) {
        int i = base + (int)threadIdx.x + r * 256;
        if (i < n) sum += cnt[i];
    }
    #pragma unroll
    for (int off = 16; off > 0; off >>= 1)
        sum += __shfl_down_sync(0xFFFFFFFFu, sum, off);
    __shared__ int ws[8];
    int lane = threadIdx.x & 31, wid = threadIdx.x >> 5;
    if (lane == 0) ws[wid] = sum;
    __syncthreads();
    if (threadIdx.x < 8) {
        int s = ws[threadIdx.x];
        #pragma unroll
        for (int off = 4; off > 0; off >>= 1)
            s += __shfl_down_sync(0xFFu, s, off);
        if (threadIdx.x == 0) partials[blockIdx.x] = s;
    }
}

// Block b: offset = sum(partials[j<b]); local scan of its chunk; writes
// rowptr[i+1] (incl), wptr[i] (excl), dis[i] = rsqrt(cnt[i]+1).
__global__ __launch_bounds__(256)
void scan_apply_kernel(const int* __restrict__ cnt,
                       const int* __restrict__ partials,
                       int* __restrict__ rowptr,
                       int* __restrict__ wptr,
                       float* __restrict__ dis,
                       int n, int nb) {
    __shared__ int s_offset;
    __shared__ int warp_sums[8];
    int lane = threadIdx.x & 31, wid = threadIdx.x >> 5;

    // offset = exclusive sum of partials before this block
    {
        int p = ((int)threadIdx.x < blockIdx.x && (int)threadIdx.x < nb)
                    ? partials[threadIdx.x] : 0;
        #pragma unroll
        for (int off = 16; off > 0; off >>= 1)
            p += __shfl_down_sync(0xFFFFFFFFu, p, off);
        if (lane == 0) warp_sums[wid] = p;
        __syncthreads();
        if (threadIdx.x < 8) {
            int s = warp_sums[threadIdx.x];
            #pragma unroll
            for (int off = 4; off > 0; off >>= 1)
                s += __shfl_down_sync(0xFFu, s, off);
            if (threadIdx.x == 0) s_offset = s;
        }
        __syncthreads();
    }
    int offset = s_offset;
    __syncthreads();  // warp_sums reused below

    int base = blockIdx.x * SCAN_CHUNK;
    // 4 elems per thread, sequential
    int v[4], s_incl[4];
    int run = 0;
    #pragma unroll
    for (int r = 0; r < 4; r++) {
        int i = base + (int)threadIdx.x * 4 + r;
        v[r] = (i < n) ? cnt[i] : 0;
        run += v[r];
        s_incl[r] = run;
    }
    // block inclusive scan of thread totals
    int x = run;
    #pragma unroll
    for (int off = 1; off < 32; off <<= 1) {
        int t = __shfl_up_sync(0xFFFFFFFFu, x, off);
        if (lane >= off) x += t;
    }
    if (lane == 31) warp_sums[wid] = x;
    __syncthreads();
    if (threadIdx.x < 8) {
        int s = warp_sums[threadIdx.x];
        #pragma unroll
        for (int off = 1; off < 8; off <<= 1) {
            int t = __shfl_up_sync(0xFFu, s, off);
            if ((int)threadIdx.x >= off) s += t;
        }
        warp_sums[threadIdx.x] = s;
    }
    __syncthreads();
    int thread_excl = x - run + ((wid > 0) ? warp_sums[wid - 1] : 0);

    #pragma unroll
    for (int r = 0; r < 4; r++) {
        int i = base + (int)threadIdx.x * 4 + r;
        if (i < n) {
            int incl = offset + thread_excl + s_incl[r];
            rowptr[i + 1] = incl;
            wptr[i]       = incl - v[r];
            dis[i]        = rsqrtf((float)(v[r] + 1));
        }
    }
    if (blockIdx.x == 0 && threadIdx.x == 0) rowptr[0] = 0;
}

__global__ void fill_kernel(const int* __restrict__ src, const int* __restrict__ dst,
                            int e, int* __restrict__ wptr, int* __restrict__ colx) {
    int i = blockIdx.x * blockDim.x + threadIdx.x;
    if (i < e) {
        int p = atomicAdd(&wptr[dst[i]], 1);
        colx[p] = src[i];
    }
}

// ---------------------------- Type GEMM ------------------------------------
// h_type = emb @ W1, [nt,128] x [128,128]. Tiny (nt=1000). BM=64 tile.

__global__ __launch_bounds__(256)
void gemm_type_kernel(const float* __restrict__ A,
                      const float* __restrict__ W,
                      float* __restrict__ out, int n) {
    __shared__ __align__(16) float As[32][68];
    __shared__ __align__(16) float Bs[32][128];

    int tid = threadIdx.x;
    int tx = tid & 31;
    int ty = tid >> 5;
    int m0 = blockIdx.x * 64;

    float acc[8][4];
    #pragma unroll
    for (int i = 0; i < 8; i++)
        #pragma unroll
        for (int j = 0; j < 4; j++) acc[i][j] = 0.0f;

    for (int kk = 0; kk < 128; kk += 32) {
        #pragma unroll
        for (int r = 0; r < 2; r++) {
            int fi = tid + r * 256;
            int m = fi >> 3;
            int q = fi & 7;
            int row = m0 + m;
            float4 v = make_float4(0.f, 0.f, 0.f, 0.f);
            if (row < n) v = *(const float4*)(A + (size_t)row * 128 + kk + q * 4);
            As[q * 4 + 0][m] = v.x;
            As[q * 4 + 1][m] = v.y;
            As[q * 4 + 2][m] = v.z;
            As[q * 4 + 3][m] = v.w;
        }
        #pragma unroll
        for (int r = 0; r < 4; r++) {
            int fi = tid + r * 256;
            int k  = fi >> 5;
            int c4 = fi & 31;
            *(float4*)&Bs[k][c4 * 4] = *(const float4*)(W + (size_t)(kk + k) * 128 + c4 * 4);
        }
        __syncthreads();
        #pragma unroll
        for (int k = 0; k < 32; k++) {
            float4 a0 = *(const float4*)&As[k][ty * 8];
            float4 a1 = *(const float4*)&As[k][ty * 8 + 4];
            float a[8] = {a0.x, a0.y, a0.z, a0.w, a1.x, a1.y, a1.z, a1.w};
            float4 bv = *(const float4*)&Bs[k][tx * 4];
            float b[4] = {bv.x, bv.y, bv.z, bv.w};
            #pragma unroll
            for (int i = 0; i < 8; i++)
                #pragma unroll
                for (int j = 0; j < 4; j++)
                    acc[i][j] = fmaf(a[i], b[j], acc[i][j]);
        }
        __syncthreads();
    }
    #pragma unroll
    for (int i = 0; i < 8; i++) {
        int row = m0 + ty * 8 + i;
        if (row < n)
            *(float4*)(out + (size_t)row * 128 + tx * 4) =
                make_float4(acc[i][0], acc[i][1], acc[i][2], acc[i][3]);
    }
}

// ---------------------------- Fused layer-1 aggregation ---------------------
// One warp per dst node. acc = dis[d]*ht[type[d]] + sum_s dis[s]*ht[type[s]];
// a1[d] = relu(dis[d]*acc + b1). ht is 512KB -> L1/L2 resident.

__global__ __launch_bounds__(256)
void agg1_fused_kernel(const float* __restrict__ ht,
                       const int* __restrict__ types,
                       const int* __restrict__ rowptr,
                       const int* __restrict__ colx,
                       const float* __restrict__ dis,
                       const float* __restrict__ bias,
                       float* __restrict__ out, int n) {
    int w = (int)((blockIdx.x * blockDim.x + threadIdx.x) >> 5);
    int lane = threadIdx.x & 31;
    if (w >= n) return;

    float dd = __ldg(&dis[w]);
    int   td = __ldg(&types[w]);
    float4 v0 = __ldg((const float4*)(ht + (size_t)td * 128) + lane);
    float ax = dd * v0.x, ay = dd * v0.y, az = dd * v0.z, aw = dd * v0.w;

    int j  = __ldg(&rowptr[w]);
    int j1 = __ldg(&rowptr[w + 1]);
    while (j < j1) {
        int m = j1 - j;
        if (m > 32) m = 32;
        int t = 0;
        float ds = 0.0f;
        if (lane < m) {
            int s = __ldg(&colx[j + lane]);
            t  = __ldg(&types[s]);
            ds = __ldg(&dis[s]);
        }
        int b = 0;
        for (; b + 1 < m; b += 2) {
            int   tA = __shfl_sync(0xFFFFFFFFu, t,  b);
            float dA = __shfl_sync(0xFFFFFFFFu, ds, b);
            int   tB = __shfl_sync(0xFFFFFFFFu, t,  b + 1);
            float dB = __shfl_sync(0xFFFFFFFFu, ds, b + 1);
            float4 vA = __ldg((const float4*)(ht + (size_t)tA * 128) + lane);
            float4 vB = __ldg((const float4*)(ht + (size_t)tB * 128) + lane);
            ax = fmaf(dA, vA.x, ax); ay = fmaf(dA, vA.y, ay);
            az = fmaf(dA, vA.z, az); aw = fmaf(dA, vA.w, aw);
            ax = fmaf(dB, vB.x, ax); ay = fmaf(dB, vB.y, ay);
            az = fmaf(dB, vB.z, az); aw = fmaf(dB, vB.w, aw);
        }
        if (b < m) {
            int   tA = __shfl_sync(0xFFFFFFFFu, t,  b);
            float dA = __shfl_sync(0xFFFFFFFFu, ds, b);
            float4 vA = __ldg((const float4*)(ht + (size_t)tA * 128) + lane);
            ax = fmaf(dA, vA.x, ax); ay = fmaf(dA, vA.y, ay);
            az = fmaf(dA, vA.z, az); aw = fmaf(dA, vA.w, aw);
        }
        j += m;
    }

    float4 bb = __ldg((const float4*)bias + lane);
    float4 res = make_float4(fmaxf(fmaf(dd, ax, bb.x), 0.0f),
                             fmaxf(fmaf(dd, ay, bb.y), 0.0f),
                             fmaxf(fmaf(dd, az, bb.z), 0.0f),
                             fmaxf(fmaf(dd, aw, bb.w), 0.0f));
    ((float4*)(out + (size_t)w * 128))[lane] = res;
}

// ---------------------------- Layer-2 GEMM ----------------------------------
// h2[row] = dis[row] * (a1[row] @ W2). [n,128] x [128,64].
// BM=128, BN=64, BK=32, 256 threads, 8x4 per-thread tile.

__global__ __launch_bounds__(256)
void gemm2_kernel(const float* __restrict__ A,
                  const float* __restrict__ W,
                  const float* __restrict__ dis,
                  float* __restrict__ out, int n) {
    __shared__ __align__(16) float As[32][132];
    __shared__ __align__(16) float Bs[32][64];

    int tid = threadIdx.x;
    int tx = tid & 15;
    int ty = tid >> 4;
    int m0 = blockIdx.x * 128;

    float acc[8][4];
    #pragma unroll
    for (int i = 0; i < 8; i++)
        #pragma unroll
        for (int j = 0; j < 4; j++) acc[i][j] = 0.0f;

    for (int kk = 0; kk < 128; kk += 32) {
        #pragma unroll
        for (int r = 0; r < 4; r++) {
            int fi = tid + r * 256;
            int m = fi >> 3;
            int q = fi & 7;
            int row = m0 + m;
            float4 v = make_float4(0.f, 0.f, 0.f, 0.f);
            if (row < n) v = *(const float4*)(A + (size_t)row * 128 + kk + q * 4);
            As[q * 4 + 0][m] = v.x;
            As[q * 4 + 1][m] = v.y;
            As[q * 4 + 2][m] = v.z;
            As[q * 4 + 3][m] = v.w;
        }
        #pragma unroll
        for (int r = 0; r < 2; r++) {
            int fi = tid + r * 256;
            int k  = fi >> 4;
            int c4 = fi & 15;
            *(float4*)&Bs[k][c4 * 4] = *(const float4*)(W + (size_t)(kk + k) * 64 + c4 * 4);
        }
        __syncthreads();
        #pragma unroll
        for (int k = 0; k < 32; k++) {
            float4 a0 = *(const float4*)&As[k][ty * 8];
            float4 a1 = *(const float4*)&As[k][ty * 8 + 4];
            float a[8] = {a0.x, a0.y, a0.z, a0.w, a1.x, a1.y, a1.z, a1.w};
            float4 bv = *(const float4*)&Bs[k][tx * 4];
            float b[4] = {bv.x, bv.y, bv.z, bv.w};
            #pragma unroll
            for (int i = 0; i < 8; i++)
                #pragma unroll
                for (int j = 0; j < 4; j++)
                    acc[i][j] = fmaf(a[i], b[j], acc[i][j]);
        }
        __syncthreads();
    }

    #pragma unroll
    for (int i = 0; i < 8; i++) {
        int row = m0 + ty * 8 + i;
        if (row < n) {
            float sc = dis[row];
            *(float4*)(out + (size_t)row * 64 + tx * 4) =
                make_float4(sc * acc[i][0], sc * acc[i][1],
                            sc * acc[i][2], sc * acc[i][3]);
        }
    }
}

// ---------------------------- Layer-2 aggregation ---------------------------

__global__ __launch_bounds__(256)
void agg2_kernel(const float* __restrict__ h,
                 const int* __restrict__ rowptr,
                 const int* __restrict__ colx,
                 const float* __restrict__ dis,
                 const float* __restrict__ bias,
                 float* __restrict__ out, int n) {
    int w = (int)((blockIdx.x * blockDim.x + threadIdx.x) >> 5);
    int lane = threadIdx.x & 31;
    if (w >= n) return;

    float2 acc;
    {
        float2 v = *(const float2*)(h + (size_t)w * 64 + lane * 2);
        acc.x = v.x; acc.y = v.y;
    }
    int j  = __ldg(&rowptr[w]);
    int j1 = __ldg(&rowptr[w + 1]);
    for (; j + 1 < j1; j += 2) {
        int sA = __ldg(&colx[j]);
        int sB = __ldg(&colx[j + 1]);
        float2 va = __ldg((const float2*)(h + (size_t)sA * 64 + lane * 2));
        float2 vb = __ldg((const float2*)(h + (size_t)sB * 64 + lane * 2));
        acc.x += va.x + vb.x;
        acc.y += va.y + vb.y;
    }
    if (j < j1) {
        int s = __ldg(&colx[j]);
        float2 v = __ldg((const float2*)(h + (size_t)s * 64 + lane * 2));
        acc.x += v.x;
        acc.y += v.y;
    }
    float sc = dis[w];
    float2 bb = *(const float2*)(bias + lane * 2);
    *(float2*)(out + (size_t)w * 64 + lane * 2) =
        make_float2(fmaf(sc, acc.x, bb.x), fmaf(sc, acc.y, bb.y));
}

// ---------------------------- Launch ----------------------------------------

extern "C" void kernel_launch(void* const* d_in, const int* in_sizes, int n_in,
                              void* d_out, int out_size) {
    const int*   types = (const int*)d_in[0];
    const int*   ei    = (const int*)d_in[1];
    const float* emb   = (const float*)d_in[2];
    const float* W1    = (const float*)d_in[3];
    const float* b1    = (const float*)d_in[4];
    const float* W2    = (const float*)d_in[5];
    const float* b2    = (const float*)d_in[6];
    float* out = (float*)d_out;

    int n  = in_sizes[0];
    int e  = in_sizes[1] / 2;
    int nt = in_sizes[2] / 128;
    if (n > MAXN) n = MAXN;
    if (e > MAXE) e = MAXE;
    if (nt > MAXT) nt = MAXT;
    const int* src = ei;
    const int* dst = ei + e;

    int *cnt, *rowptr, *wptr, *colx, *partials;
    float *dis, *ht, *a1, *h2;
    cudaGetSymbolAddress((void**)&cnt,      g_cnt);
    cudaGetSymbolAddress((void**)&rowptr,   g_rowptr);
    cudaGetSymbolAddress((void**)&wptr,     g_wptr);
    cudaGetSymbolAddress((void**)&colx,     g_col);
    cudaGetSymbolAddress((void**)&partials, g_partials);
    cudaGetSymbolAddress((void**)&dis,      g_dis);
    cudaGetSymbolAddress((void**)&ht,       g_ht);
    cudaGetSymbolAddress((void**)&a1,       g_a1);
    cudaGetSymbolAddress((void**)&h2,       g_h2);

    int nb_e = (e + 255) / 256;
    int nb   = (n + SCAN_CHUNK - 1) / SCAN_CHUNK;   // 98 blocks

    // h_type = emb @ W1 (independent of CSR build)
    gemm_type_kernel<<<(nt + 63) / 64, 256>>>(emb, W1, ht, nt);

    // CSR build: memset + count + multiblock scan (dis fused) + fill
    cudaMemsetAsync(cnt, 0, (size_t)n * sizeof(int));
    count_kernel<<<nb_e, 256>>>(dst, e, cnt);
    blocksum_kernel<<<nb, 256>>>(cnt, partials, n);
    scan_apply_kernel<<<nb, 256>>>(cnt, partials, rowptr, wptr, dis, n, nb);
    fill_kernel<<<nb_e, 256>>>(src, dst, e, wptr, colx);

    int agg_blocks = (n + 7) / 8;

    // Layer 1: fused gather + aggregate from h_type table
    agg1_fused_kernel<<<agg_blocks, 256>>>(ht, types, rowptr, colx, dis, b1, a1, n);

    // Layer 2
    gemm2_kernel<<<(n + 127) / 128, 256>>>(a1, W2, dis, h2, n);
    agg2_kernel<<<agg_blocks, 256>>>(h2, rowptr, colx, dis, b2, out, n);
}

// round 4
// speedup vs baseline: 1.8440x; 1.0686x over previous
#include <cuda_runtime.h>
#include <cuda_fp16.h>

// ---------------------------------------------------------------------------
// GCNEncoder: 2-layer GCN, N=100000, E=1600000, 1000 node types.
// h_type = emb @ W1 is only [1000,128]; layer-1 agg gathers dis[s]*ht[type[s]].
// Round 4: ht and h2 stored as fp16 (fp32 accumulation) to halve the
// L2-gather traffic of both aggregation kernels (the measured bottleneck).
// ---------------------------------------------------------------------------

#define MAXN 100000
#define MAXE 1600000
#define MAXT 4096
#define SCAN_CHUNK 1024
#define MAXNB ((MAXN + SCAN_CHUNK - 1) / SCAN_CHUNK)

__device__ int    g_cnt[MAXN];
__device__ int    g_rowptr[MAXN + 1];
__device__ int    g_wptr[MAXN];
__device__ int    g_col[MAXE];
__device__ int    g_partials[MAXNB];
__device__ float  g_dis[MAXN];
__device__ __half g_ht[(size_t)MAXT * 128];    // h_type = emb @ W1 (fp16)
__device__ float  g_a1[(size_t)MAXN * 128];    // relu layer-1 output (fp32)
__device__ __half g_h2[(size_t)MAXN * 64];     // dis * (a1 @ W2) (fp16)

// ---------------------------- CSR build -----------------------------------

__global__ void count_kernel(const int* __restrict__ dst, int e, int* __restrict__ cnt) {
    int i = blockIdx.x * blockDim.x + threadIdx.x;
    if (i < e) atomicAdd(&cnt[dst[i]], 1);
}

__global__ __launch_bounds__(256)
void blocksum_kernel(const int* __restrict__ cnt, int* __restrict__ partials, int n) {
    int base = blockIdx.x * SCAN_CHUNK;
    int sum = 0;
    #pragma unroll
    for (int r = 0; r < 4; r++) {
        int i = base + (int)threadIdx.x + r * 256;
        if (i < n) sum += cnt[i];
    }
    #pragma unroll
    for (int off = 16; off > 0; off >>= 1)
        sum += __shfl_down_sync(0xFFFFFFFFu, sum, off);
    __shared__ int ws[8];
    int lane = threadIdx.x & 31, wid = threadIdx.x >> 5;
    if (lane == 0) ws[wid] = sum;
    __syncthreads();
    if (threadIdx.x < 8) {
        int s = ws[threadIdx.x];
        #pragma unroll
        for (int off = 4; off > 0; off >>= 1)
            s += __shfl_down_sync(0xFFu, s, off);
        if (threadIdx.x == 0) partials[blockIdx.x] = s;
    }
}

__global__ __launch_bounds__(256)
void scan_apply_kernel(const int* __restrict__ cnt,
                       const int* __restrict__ partials,
                       int* __restrict__ rowptr,
                       int* __restrict__ wptr,
                       float* __restrict__ dis,
                       int n, int nb) {
    __shared__ int s_offset;
    __shared__ int warp_sums[8];
    int lane = threadIdx.x & 31, wid = threadIdx.x >> 5;

    {
        int p = ((int)threadIdx.x < blockIdx.x && (int)threadIdx.x < nb)
                    ? partials[threadIdx.x] : 0;
        #pragma unroll
        for (int off = 16; off > 0; off >>= 1)
            p += __shfl_down_sync(0xFFFFFFFFu, p, off);
        if (lane == 0) warp_sums[wid] = p;
        __syncthreads();
        if (threadIdx.x < 8) {
            int s = warp_sums[threadIdx.x];
            #pragma unroll
            for (int off = 4; off > 0; off >>= 1)
                s += __shfl_down_sync(0xFFu, s, off);
            if (threadIdx.x == 0) s_offset = s;
        }
        __syncthreads();
    }
    int offset = s_offset;
    __syncthreads();

    int base = blockIdx.x * SCAN_CHUNK;
    int v[4], s_incl[4];
    int run = 0;
    #pragma unroll
    for (int r = 0; r < 4; r++) {
        int i = base + (int)threadIdx.x * 4 + r;
        v[r] = (i < n) ? cnt[i] : 0;
        run += v[r];
        s_incl[r] = run;
    }
    int x = run;
    #pragma unroll
    for (int off = 1; off < 32; off <<= 1) {
        int t = __shfl_up_sync(0xFFFFFFFFu, x, off);
        if (lane >= off) x += t;
    }
    if (lane == 31) warp_sums[wid] = x;
    __syncthreads();
    if (threadIdx.x < 8) {
        int s = warp_sums[threadIdx.x];
        #pragma unroll
        for (int off = 1; off < 8; off <<= 1) {
            int t = __shfl_up_sync(0xFFu, s, off);
            if ((int)threadIdx.x >= off) s += t;
        }
        warp_sums[threadIdx.x] = s;
    }
    __syncthreads();
    int thread_excl = x - run + ((wid > 0) ? warp_sums[wid - 1] : 0);

    #pragma unroll
    for (int r = 0; r < 4; r++) {
        int i = base + (int)threadIdx.x * 4 + r;
        if (i < n) {
            int incl = offset + thread_excl + s_incl[r];
            rowptr[i + 1] = incl;
            wptr[i]       = incl - v[r];
            dis[i]        = rsqrtf((float)(v[r] + 1));
        }
    }
    if (blockIdx.x == 0 && threadIdx.x == 0) rowptr[0] = 0;
}

__global__ void fill_kernel(const int* __restrict__ src, const int* __restrict__ dst,
                            int e, int* __restrict__ wptr, int* __restrict__ colx) {
    int i = blockIdx.x * blockDim.x + threadIdx.x;
    if (i < e) {
        int p = atomicAdd(&wptr[dst[i]], 1);
        colx[p] = src[i];
    }
}

// ---------------------------- Type GEMM ------------------------------------
// ht = fp16(emb @ W1), [nt,128] x [128,128].

__global__ __launch_bounds__(256)
void gemm_type_kernel(const float* __restrict__ A,
                      const float* __restrict__ W,
                      __half* __restrict__ out, int n) {
    __shared__ __align__(16) float As[32][68];
    __shared__ __align__(16) float Bs[32][128];

    int tid = threadIdx.x;
    int tx = tid & 31;
    int ty = tid >> 5;
    int m0 = blockIdx.x * 64;

    float acc[8][4];
    #pragma unroll
    for (int i = 0; i < 8; i++)
        #pragma unroll
        for (int j = 0; j < 4; j++) acc[i][j] = 0.0f;

    for (int kk = 0; kk < 128; kk += 32) {
        #pragma unroll
        for (int r = 0; r < 2; r++) {
            int fi = tid + r * 256;
            int m = fi >> 3;
            int q = fi & 7;
            int row = m0 + m;
            float4 v = make_float4(0.f, 0.f, 0.f, 0.f);
            if (row < n) v = *(const float4*)(A + (size_t)row * 128 + kk + q * 4);
            As[q * 4 + 0][m] = v.x;
            As[q * 4 + 1][m] = v.y;
            As[q * 4 + 2][m] = v.z;
            As[q * 4 + 3][m] = v.w;
        }
        #pragma unroll
        for (int r = 0; r < 4; r++) {
            int fi = tid + r * 256;
            int k  = fi >> 5;
            int c4 = fi & 31;
            *(float4*)&Bs[k][c4 * 4] = *(const float4*)(W + (size_t)(kk + k) * 128 + c4 * 4);
        }
        __syncthreads();
        #pragma unroll
        for (int k = 0; k < 32; k++) {
            float4 a0 = *(const float4*)&As[k][ty * 8];
            float4 a1 = *(const float4*)&As[k][ty * 8 + 4];
            float a[8] = {a0.x, a0.y, a0.z, a0.w, a1.x, a1.y, a1.z, a1.w};
            float4 bv = *(const float4*)&Bs[k][tx * 4];
            float b[4] = {bv.x, bv.y, bv.z, bv.w};
            #pragma unroll
            for (int i = 0; i < 8; i++)
                #pragma unroll
                for (int j = 0; j < 4; j++)
                    acc[i][j] = fmaf(a[i], b[j], acc[i][j]);
        }
        __syncthreads();
    }
    #pragma unroll
    for (int i = 0; i < 8; i++) {
        int row = m0 + ty * 8 + i;
        if (row < n) {
            __half2 h0 = __floats2half2_rn(acc[i][0], acc[i][1]);
            __half2 h1 = __floats2half2_rn(acc[i][2], acc[i][3]);
            uint2 u = make_uint2(*(unsigned*)&h0, *(unsigned*)&h1);
            *(uint2*)(out + (size_t)row * 128 + tx * 4) = u;
        }
    }
}

// ---------------------------- Fused layer-1 aggregation ---------------------
// One warp per dst node. ht is fp16 [T,128] (256KB). Lane covers 4 cols:
// one uint2 (4 halves) per gathered row. fp32 accumulate.

__global__ __launch_bounds__(256)
void agg1_fused_kernel(const __half* __restrict__ ht,
                       const int* __restrict__ types,
                       const int* __restrict__ rowptr,
                       const int* __restrict__ colx,
                       const float* __restrict__ dis,
                       const float* __restrict__ bias,
                       float* __restrict__ out, int n) {
    int w = (int)((blockIdx.x * blockDim.x + threadIdx.x) >> 5);
    int lane = threadIdx.x & 31;
    if (w >= n) return;

    float dd = __ldg(&dis[w]);
    int   td = __ldg(&types[w]);
    float ax, ay, az, aw;
    {
        uint2 u = __ldg((const uint2*)(ht + (size_t)td * 128) + lane);
        float2 f0 = __half22float2(*(__half2*)&u.x);
        float2 f1 = __half22float2(*(__half2*)&u.y);
        ax = dd * f0.x; ay = dd * f0.y; az = dd * f1.x; aw = dd * f1.y;
    }

    int j  = __ldg(&rowptr[w]);
    int j1 = __ldg(&rowptr[w + 1]);
    while (j < j1) {
        int m = j1 - j;
        if (m > 32) m = 32;
        int t = 0;
        float ds = 0.0f;
        if (lane < m) {
            int s = __ldg(&colx[j + lane]);
            t  = __ldg(&types[s]);
            ds = __ldg(&dis[s]);
        }
        int b = 0;
        for (; b + 1 < m; b += 2) {
            int   tA = __shfl_sync(0xFFFFFFFFu, t,  b);
            float dA = __shfl_sync(0xFFFFFFFFu, ds, b);
            int   tB = __shfl_sync(0xFFFFFFFFu, t,  b + 1);
            float dB = __shfl_sync(0xFFFFFFFFu, ds, b + 1);
            uint2 uA = __ldg((const uint2*)(ht + (size_t)tA * 128) + lane);
            uint2 uB = __ldg((const uint2*)(ht + (size_t)tB * 128) + lane);
            float2 a0 = __half22float2(*(__half2*)&uA.x);
            float2 a1 = __half22float2(*(__half2*)&uA.y);
            float2 b0 = __half22float2(*(__half2*)&uB.x);
            float2 b1 = __half22float2(*(__half2*)&uB.y);
            ax = fmaf(dA, a0.x, ax); ay = fmaf(dA, a0.y, ay);
            az = fmaf(dA, a1.x, az); aw = fmaf(dA, a1.y, aw);
            ax = fmaf(dB, b0.x, ax); ay = fmaf(dB, b0.y, ay);
            az = fmaf(dB, b1.x, az); aw = fmaf(dB, b1.y, aw);
        }
        if (b < m) {
            int   tA = __shfl_sync(0xFFFFFFFFu, t,  b);
            float dA = __shfl_sync(0xFFFFFFFFu, ds, b);
            uint2 uA = __ldg((const uint2*)(ht + (size_t)tA * 128) + lane);
            float2 a0 = __half22float2(*(__half2*)&uA.x);
            float2 a1 = __half22float2(*(__half2*)&uA.y);
            ax = fmaf(dA, a0.x, ax); ay = fmaf(dA, a0.y, ay);
            az = fmaf(dA, a1.x, az); aw = fmaf(dA, a1.y, aw);
        }
        j += m;
    }

    float4 bb = __ldg((const float4*)bias + lane);
    float4 res = make_float4(fmaxf(fmaf(dd, ax, bb.x), 0.0f),
                             fmaxf(fmaf(dd, ay, bb.y), 0.0f),
                             fmaxf(fmaf(dd, az, bb.z), 0.0f),
                             fmaxf(fmaf(dd, aw, bb.w), 0.0f));
    ((float4*)(out + (size_t)w * 128))[lane] = res;
}

// ---------------------------- Layer-2 GEMM ----------------------------------
// h2 = fp16(dis * (a1 @ W2)). [n,128] x [128,64]. BM=128, BN=64, BK=32.

__global__ __launch_bounds__(256)
void gemm2_kernel(const float* __restrict__ A,
                  const float* __restrict__ W,
                  const float* __restrict__ dis,
                  __half* __restrict__ out, int n) {
    __shared__ __align__(16) float As[32][132];
    __shared__ __align__(16) float Bs[32][64];

    int tid = threadIdx.x;
    int tx = tid & 15;
    int ty = tid >> 4;
    int m0 = blockIdx.x * 128;

    float acc[8][4];
    #pragma unroll
    for (int i = 0; i < 8; i++)
        #pragma unroll
        for (int j = 0; j < 4; j++) acc[i][j] = 0.0f;

    for (int kk = 0; kk < 128; kk += 32) {
        #pragma unroll
        for (int r = 0; r < 4; r++) {
            int fi = tid + r * 256;
            int m = fi >> 3;
            int q = fi & 7;
            int row = m0 + m;
            float4 v = make_float4(0.f, 0.f, 0.f, 0.f);
            if (row < n) v = *(const float4*)(A + (size_t)row * 128 + kk + q * 4);
            As[q * 4 + 0][m] = v.x;
            As[q * 4 + 1][m] = v.y;
            As[q * 4 + 2][m] = v.z;
            As[q * 4 + 3][m] = v.w;
        }
        #pragma unroll
        for (int r = 0; r < 2; r++) {
            int fi = tid + r * 256;
            int k  = fi >> 4;
            int c4 = fi & 15;
            *(float4*)&Bs[k][c4 * 4] = *(const float4*)(W + (size_t)(kk + k) * 64 + c4 * 4);
        }
        __syncthreads();
        #pragma unroll
        for (int k = 0; k < 32; k++) {
            float4 a0 = *(const float4*)&As[k][ty * 8];
            float4 a1 = *(const float4*)&As[k][ty * 8 + 4];
            float a[8] = {a0.x, a0.y, a0.z, a0.w, a1.x, a1.y, a1.z, a1.w};
            float4 bv = *(const float4*)&Bs[k][tx * 4];
            float b[4] = {bv.x, bv.y, bv.z, bv.w};
            #pragma unroll
            for (int i = 0; i < 8; i++)
                #pragma unroll
                for (int j = 0; j < 4; j++)
                    acc[i][j] = fmaf(a[i], b[j], acc[i][j]);
        }
        __syncthreads();
    }

    #pragma unroll
    for (int i = 0; i < 8; i++) {
        int row = m0 + ty * 8 + i;
        if (row < n) {
            float sc = dis[row];
            __half2 h0 = __floats2half2_rn(sc * acc[i][0], sc * acc[i][1]);
            __half2 h1 = __floats2half2_rn(sc * acc[i][2], sc * acc[i][3]);
            uint2 u = make_uint2(*(unsigned*)&h0, *(unsigned*)&h1);
            *(uint2*)(out + (size_t)row * 64 + tx * 4) = u;
        }
    }
}

// ---------------------------- Layer-2 aggregation ---------------------------
// h2 fp16 [n,64]: one row = 128B = a single L2 line per gathered edge.

__global__ __launch_bounds__(256)
void agg2_kernel(const __half* __restrict__ h,
                 const int* __restrict__ rowptr,
                 const int* __restrict__ colx,
                 const float* __restrict__ dis,
                 const float* __restrict__ bias,
                 float* __restrict__ out, int n) {
    int w = (int)((blockIdx.x * blockDim.x + threadIdx.x) >> 5);
    int lane = threadIdx.x & 31;
    if (w >= n) return;

    float2 acc;
    {
        unsigned u = __ldg((const unsigned*)(h + (size_t)w * 64) + lane);
        acc = __half22float2(*(__half2*)&u);
    }
    int j  = __ldg(&rowptr[w]);
    int j1 = __ldg(&rowptr[w + 1]);
    for (; j + 1 < j1; j += 2) {
        int sA = __ldg(&colx[j]);
        int sB = __ldg(&colx[j + 1]);
        unsigned uA = __ldg((const unsigned*)(h + (size_t)sA * 64) + lane);
        unsigned uB = __ldg((const unsigned*)(h + (size_t)sB * 64) + lane);
        float2 va = __half22float2(*(__half2*)&uA);
        float2 vb = __half22float2(*(__half2*)&uB);
        acc.x += va.x + vb.x;
        acc.y += va.y + vb.y;
    }
    if (j < j1) {
        int s = __ldg(&colx[j]);
        unsigned u = __ldg((const unsigned*)(h + (size_t)s * 64) + lane);
        float2 v = __half22float2(*(__half2*)&u);
        acc.x += v.x;
        acc.y += v.y;
    }
    float sc = dis[w];
    float2 bb = *(const float2*)(bias + lane * 2);
    *(float2*)(out + (size_t)w * 64 + lane * 2) =
        make_float2(fmaf(sc, acc.x, bb.x), fmaf(sc, acc.y, bb.y));
}

// ---------------------------- Launch ----------------------------------------

extern "C" void kernel_launch(void* const* d_in, const int* in_sizes, int n_in,
                              void* d_out, int out_size) {
    const int*   types = (const int*)d_in[0];
    const int*   ei    = (const int*)d_in[1];
    const float* emb   = (const float*)d_in[2];
    const float* W1    = (const float*)d_in[3];
    const float* b1    = (const float*)d_in[4];
    const float* W2    = (const float*)d_in[5];
    const float* b2    = (const float*)d_in[6];
    float* out = (float*)d_out;

    int n  = in_sizes[0];
    int e  = in_sizes[1] / 2;
    int nt = in_sizes[2] / 128;
    if (n > MAXN) n = MAXN;
    if (e > MAXE) e = MAXE;
    if (nt > MAXT) nt = MAXT;
    const int* src = ei;
    const int* dst = ei + e;

    int *cnt, *rowptr, *wptr, *colx, *partials;
    float *dis, *a1;
    __half *ht, *h2;
    cudaGetSymbolAddress((void**)&cnt,      g_cnt);
    cudaGetSymbolAddress((void**)&rowptr,   g_rowptr);
    cudaGetSymbolAddress((void**)&wptr,     g_wptr);
    cudaGetSymbolAddress((void**)&colx,     g_col);
    cudaGetSymbolAddress((void**)&partials, g_partials);
    cudaGetSymbolAddress((void**)&dis,      g_dis);
    cudaGetSymbolAddress((void**)&ht,       g_ht);
    cudaGetSymbolAddress((void**)&a1,       g_a1);
    cudaGetSymbolAddress((void**)&h2,       g_h2);

    int nb_e = (e + 255) / 256;
    int nb   = (n + SCAN_CHUNK - 1) / SCAN_CHUNK;

    gemm_type_kernel<<<(nt + 63) / 64, 256>>>(emb, W1, ht, nt);

    cudaMemsetAsync(cnt, 0, (size_t)n * sizeof(int));
    count_kernel<<<nb_e, 256>>>(dst, e, cnt);
    blocksum_kernel<<<nb, 256>>>(cnt, partials, n);
    scan_apply_kernel<<<nb, 256>>>(cnt, partials, rowptr, wptr, dis, n, nb);
    fill_kernel<<<nb_e, 256>>>(src, dst, e, wptr, colx);

    int agg_blocks = (n + 7) / 8;

    agg1_fused_kernel<<<agg_blocks, 256>>>(ht, types, rowptr, colx, dis, b1, a1, n);

    gemm2_kernel<<<(n + 127) / 128, 256>>>(a1, W2, dis, h2, n);
    agg2_kernel<<<agg_blocks, 256>>>(h2, rowptr, colx, dis, b2, out, n);
}

// round 5
// speedup vs baseline: 2.2115x; 1.1993x over previous
#include <cuda_runtime.h>
#include <cuda_fp16.h>
#include <mma.h>

using namespace nvcuda;

// ---------------------------------------------------------------------------
// GCNEncoder: 2-layer GCN, N=100000, E=1600000, 1000 node types.
// Round 5: gemm2 on tensor cores (wmma fp16 -> fp32 accum). agg1 stores
// a1s = fp16(dis * relu(...)) so layer-2's source-side dis prescale is folded
// into the GEMM input (row scaling commutes with GEMM) and gemm2 has no
// epilogue scaling at all.
// ---------------------------------------------------------------------------

#define MAXN 100000
#define MAXE 1600000
#define MAXT 4096
#define SCAN_CHUNK 1024
#define MAXNB ((MAXN + SCAN_CHUNK - 1) / SCAN_CHUNK)

__device__ int    g_cnt[MAXN];
__device__ int    g_rowptr[MAXN + 1];
__device__ int    g_wptr[MAXN];
__device__ int    g_col[MAXE];
__device__ int    g_partials[MAXNB];
__device__ float  g_dis[MAXN];
__device__ __half g_ht[(size_t)MAXT * 128];      // h_type = emb @ W1 (fp16)
__device__ __half g_a1s[(size_t)MAXN * 128];     // dis * relu(layer1) (fp16)
__device__ __half g_w2h[128 * 64];               // W2 in fp16
// h2 rows are written by full 64-row GEMM tiles (up to 100032 rows) — pad.
__device__ __half g_h2[(size_t)(MAXN + 64) * 64];

// ---------------------------- CSR build -----------------------------------

__global__ void count_kernel(const int* __restrict__ dst, int e, int* __restrict__ cnt) {
    int i = blockIdx.x * blockDim.x + threadIdx.x;
    if (i < e) atomicAdd(&cnt[dst[i]], 1);
}

__global__ __launch_bounds__(256)
void blocksum_kernel(const int* __restrict__ cnt, int* __restrict__ partials, int n) {
    int base = blockIdx.x * SCAN_CHUNK;
    int sum = 0;
    #pragma unroll
    for (int r = 0; r < 4; r++) {
        int i = base + (int)threadIdx.x + r * 256;
        if (i < n) sum += cnt[i];
    }
    #pragma unroll
    for (int off = 16; off > 0; off >>= 1)
        sum += __shfl_down_sync(0xFFFFFFFFu, sum, off);
    __shared__ int ws[8];
    int lane = threadIdx.x & 31, wid = threadIdx.x >> 5;
    if (lane == 0) ws[wid] = sum;
    __syncthreads();
    if (threadIdx.x < 8) {
        int s = ws[threadIdx.x];
        #pragma unroll
        for (int off = 4; off > 0; off >>= 1)
            s += __shfl_down_sync(0xFFu, s, off);
        if (threadIdx.x == 0) partials[blockIdx.x] = s;
    }
}

__global__ __launch_bounds__(256)
void scan_apply_kernel(const int* __restrict__ cnt,
                       const int* __restrict__ partials,
                       int* __restrict__ rowptr,
                       int* __restrict__ wptr,
                       float* __restrict__ dis,
                       int n, int nb) {
    __shared__ int s_offset;
    __shared__ int warp_sums[8];
    int lane = threadIdx.x & 31, wid = threadIdx.x >> 5;

    {
        int p = ((int)threadIdx.x < blockIdx.x && (int)threadIdx.x < nb)
                    ? partials[threadIdx.x] : 0;
        #pragma unroll
        for (int off = 16; off > 0; off >>= 1)
            p += __shfl_down_sync(0xFFFFFFFFu, p, off);
        if (lane == 0) warp_sums[wid] = p;
        __syncthreads();
        if (threadIdx.x < 8) {
            int s = warp_sums[threadIdx.x];
            #pragma unroll
            for (int off = 4; off > 0; off >>= 1)
                s += __shfl_down_sync(0xFFu, s, off);
            if (threadIdx.x == 0) s_offset = s;
        }
        __syncthreads();
    }
    int offset = s_offset;
    __syncthreads();

    int base = blockIdx.x * SCAN_CHUNK;
    int v[4], s_incl[4];
    int run = 0;
    #pragma unroll
    for (int r = 0; r < 4; r++) {
        int i = base + (int)threadIdx.x * 4 + r;
        v[r] = (i < n) ? cnt[i] : 0;
        run += v[r];
        s_incl[r] = run;
    }
    int x = run;
    #pragma unroll
    for (int off = 1; off < 32; off <<= 1) {
        int t = __shfl_up_sync(0xFFFFFFFFu, x, off);
        if (lane >= off) x += t;
    }
    if (lane == 31) warp_sums[wid] = x;
    __syncthreads();
    if (threadIdx.x < 8) {
        int s = warp_sums[threadIdx.x];
        #pragma unroll
        for (int off = 1; off < 8; off <<= 1) {
            int t = __shfl_up_sync(0xFFu, s, off);
            if ((int)threadIdx.x >= off) s += t;
        }
        warp_sums[threadIdx.x] = s;
    }
    __syncthreads();
    int thread_excl = x - run + ((wid > 0) ? warp_sums[wid - 1] : 0);

    #pragma unroll
    for (int r = 0; r < 4; r++) {
        int i = base + (int)threadIdx.x * 4 + r;
        if (i < n) {
            int incl = offset + thread_excl + s_incl[r];
            rowptr[i + 1] = incl;
            wptr[i]       = incl - v[r];
            dis[i]        = rsqrtf((float)(v[r] + 1));
        }
    }
    if (blockIdx.x == 0 && threadIdx.x == 0) rowptr[0] = 0;
}

__global__ void fill_kernel(const int* __restrict__ src, const int* __restrict__ dst,
                            int e, int* __restrict__ wptr, int* __restrict__ colx) {
    int i = blockIdx.x * blockDim.x + threadIdx.x;
    if (i < e) {
        int p = atomicAdd(&wptr[dst[i]], 1);
        colx[p] = src[i];
    }
}

// ---------------------------- Type GEMM ------------------------------------

__global__ __launch_bounds__(256)
void gemm_type_kernel(const float* __restrict__ A,
                      const float* __restrict__ W,
                      __half* __restrict__ out, int n) {
    __shared__ __align__(16) float As[32][68];
    __shared__ __align__(16) float Bs[32][128];

    int tid = threadIdx.x;
    int tx = tid & 31;
    int ty = tid >> 5;
    int m0 = blockIdx.x * 64;

    float acc[8][4];
    #pragma unroll
    for (int i = 0; i < 8; i++)
        #pragma unroll
        for (int j = 0; j < 4; j++) acc[i][j] = 0.0f;

    for (int kk = 0; kk < 128; kk += 32) {
        #pragma unroll
        for (int r = 0; r < 2; r++) {
            int fi = tid + r * 256;
            int m = fi >> 3;
            int q = fi & 7;
            int row = m0 + m;
            float4 v = make_float4(0.f, 0.f, 0.f, 0.f);
            if (row < n) v = *(const float4*)(A + (size_t)row * 128 + kk + q * 4);
            As[q * 4 + 0][m] = v.x;
            As[q * 4 + 1][m] = v.y;
            As[q * 4 + 2][m] = v.z;
            As[q * 4 + 3][m] = v.w;
        }
        #pragma unroll
        for (int r = 0; r < 4; r++) {
            int fi = tid + r * 256;
            int k  = fi >> 5;
            int c4 = fi & 31;
            *(float4*)&Bs[k][c4 * 4] = *(const float4*)(W + (size_t)(kk + k) * 128 + c4 * 4);
        }
        __syncthreads();
        #pragma unroll
        for (int k = 0; k < 32; k++) {
            float4 a0 = *(const float4*)&As[k][ty * 8];
            float4 a1 = *(const float4*)&As[k][ty * 8 + 4];
            float a[8] = {a0.x, a0.y, a0.z, a0.w, a1.x, a1.y, a1.z, a1.w};
            float4 bv = *(const float4*)&Bs[k][tx * 4];
            float b[4] = {bv.x, bv.y, bv.z, bv.w};
            #pragma unroll
            for (int i = 0; i < 8; i++)
                #pragma unroll
                for (int j = 0; j < 4; j++)
                    acc[i][j] = fmaf(a[i], b[j], acc[i][j]);
        }
        __syncthreads();
    }
    #pragma unroll
    for (int i = 0; i < 8; i++) {
        int row = m0 + ty * 8 + i;
        if (row < n) {
            __half2 h0 = __floats2half2_rn(acc[i][0], acc[i][1]);
            __half2 h1 = __floats2half2_rn(acc[i][2], acc[i][3]);
            uint2 u = make_uint2(*(unsigned*)&h0, *(unsigned*)&h1);
            *(uint2*)(out + (size_t)row * 128 + tx * 4) = u;
        }
    }
}

// Convert W2 [128,64] fp32 -> fp16 once.
__global__ void w2h_kernel(const float* __restrict__ W, __half* __restrict__ Wh) {
    int i = blockIdx.x * blockDim.x + threadIdx.x;
    if (i < 128 * 64) Wh[i] = __float2half(W[i]);
}

// ---------------------------- Fused layer-1 aggregation ---------------------
// One warp per dst node. Writes a1s = fp16(dis[w] * relu(dis[w]*acc + b1)).

__global__ __launch_bounds__(256)
void agg1_fused_kernel(const __half* __restrict__ ht,
                       const int* __restrict__ types,
                       const int* __restrict__ rowptr,
                       const int* __restrict__ colx,
                       const float* __restrict__ dis,
                       const float* __restrict__ bias,
                       __half* __restrict__ out, int n) {
    int w = (int)((blockIdx.x * blockDim.x + threadIdx.x) >> 5);
    int lane = threadIdx.x & 31;
    if (w >= n) return;

    float dd = __ldg(&dis[w]);
    int   td = __ldg(&types[w]);
    float ax, ay, az, aw;
    {
        uint2 u = __ldg((const uint2*)(ht + (size_t)td * 128) + lane);
        float2 f0 = __half22float2(*(__half2*)&u.x);
        float2 f1 = __half22float2(*(__half2*)&u.y);
        ax = dd * f0.x; ay = dd * f0.y; az = dd * f1.x; aw = dd * f1.y;
    }

    int j  = __ldg(&rowptr[w]);
    int j1 = __ldg(&rowptr[w + 1]);
    while (j < j1) {
        int m = j1 - j;
        if (m > 32) m = 32;
        int t = 0;
        float ds = 0.0f;
        if (lane < m) {
            int s = __ldg(&colx[j + lane]);
            t  = __ldg(&types[s]);
            ds = __ldg(&dis[s]);
        }
        int b = 0;
        for (; b + 1 < m; b += 2) {
            int   tA = __shfl_sync(0xFFFFFFFFu, t,  b);
            float dA = __shfl_sync(0xFFFFFFFFu, ds, b);
            int   tB = __shfl_sync(0xFFFFFFFFu, t,  b + 1);
            float dB = __shfl_sync(0xFFFFFFFFu, ds, b + 1);
            uint2 uA = __ldg((const uint2*)(ht + (size_t)tA * 128) + lane);
            uint2 uB = __ldg((const uint2*)(ht + (size_t)tB * 128) + lane);
            float2 a0 = __half22float2(*(__half2*)&uA.x);
            float2 a1 = __half22float2(*(__half2*)&uA.y);
            float2 b0 = __half22float2(*(__half2*)&uB.x);
            float2 b1 = __half22float2(*(__half2*)&uB.y);
            ax = fmaf(dA, a0.x, ax); ay = fmaf(dA, a0.y, ay);
            az = fmaf(dA, a1.x, az); aw = fmaf(dA, a1.y, aw);
            ax = fmaf(dB, b0.x, ax); ay = fmaf(dB, b0.y, ay);
            az = fmaf(dB, b1.x, az); aw = fmaf(dB, b1.y, aw);
        }
        if (b < m) {
            int   tA = __shfl_sync(0xFFFFFFFFu, t,  b);
            float dA = __shfl_sync(0xFFFFFFFFu, ds, b);
            uint2 uA = __ldg((const uint2*)(ht + (size_t)tA * 128) + lane);
            float2 a0 = __half22float2(*(__half2*)&uA.x);
            float2 a1 = __half22float2(*(__half2*)&uA.y);
            ax = fmaf(dA, a0.x, ax); ay = fmaf(dA, a0.y, ay);
            az = fmaf(dA, a1.x, az); aw = fmaf(dA, a1.y, aw);
        }
        j += m;
    }

    float4 bb = __ldg((const float4*)bias + lane);
    // r = relu(dd*acc + b); store dd*r (layer-2 source prescale folded in)
    float r0 = dd * fmaxf(fmaf(dd, ax, bb.x), 0.0f);
    float r1 = dd * fmaxf(fmaf(dd, ay, bb.y), 0.0f);
    float r2 = dd * fmaxf(fmaf(dd, az, bb.z), 0.0f);
    float r3 = dd * fmaxf(fmaf(dd, aw, bb.w), 0.0f);
    __half2 h0 = __floats2half2_rn(r0, r1);
    __half2 h1 = __floats2half2_rn(r2, r3);
    uint2 u = make_uint2(*(unsigned*)&h0, *(unsigned*)&h1);
    ((uint2*)(out + (size_t)w * 128))[lane] = u;
}

// ---------------------------- Layer-2 GEMM (tensor cores) -------------------
// h2[64 rows] = A_tile[64,128] @ W[128,64], all fp16 in, fp32 accum, fp16 out.
// 8 warps in 4x2 grid; each warp 16x32 (two 16x16 frags), K-loop of 8.

__global__ __launch_bounds__(256)
void gemm2_tc_kernel(const __half* __restrict__ A,
                     const __half* __restrict__ W,
                     __half* __restrict__ out, int n) {
    __shared__ __align__(16) __half As[64][136];
    __shared__ __align__(16) __half Ws[128][72];

    int tid = threadIdx.x;
    int wid = tid >> 5;
    int m0 = blockIdx.x * 64;

    // Load A tile: 64 rows x 128 halves = 1024 uint4; 4 per thread.
    #pragma unroll
    for (int r = 0; r < 4; r++) {
        int fi = tid + r * 256;
        int m = fi >> 4;          // row in tile
        int q = fi & 15;          // uint4 within row (8 halves each)
        int row = m0 + m;
        uint4 v = make_uint4(0, 0, 0, 0);
        if (row < n) v = *(const uint4*)(A + (size_t)row * 128 + q * 8);
        *(uint4*)&As[m][q * 8] = v;
    }
    // Load W: 128 x 64 halves = 1024 uint4; 4 per thread.
    #pragma unroll
    for (int r = 0; r < 4; r++) {
        int fi = tid + r * 256;
        int k  = fi >> 3;         // row of W
        int q  = fi & 7;          // uint4 within row
        *(uint4*)&Ws[k][q * 8] = *(const uint4*)(W + (size_t)k * 64 + q * 8);
    }
    __syncthreads();

    int wm = wid >> 1;            // 0..3 (16-row slice)
    int wn = wid & 1;             // 0..1 (32-col slice)

    wmma::fragment<wmma::accumulator, 16, 16, 16, float> c[2];
    wmma::fill_fragment(c[0], 0.0f);
    wmma::fill_fragment(c[1], 0.0f);

    #pragma unroll
    for (int k = 0; k < 8; k++) {
        wmma::fragment<wmma::matrix_a, 16, 16, 16, __half, wmma::row_major> af;
        wmma::load_matrix_sync(af, &As[wm * 16][k * 16], 136);
        #pragma unroll
        for (int f = 0; f < 2; f++) {
            wmma::fragment<wmma::matrix_b, 16, 16, 16, __half, wmma::row_major> bf;
            wmma::load_matrix_sync(bf, &Ws[k * 16][wn * 32 + f * 16], 72);
            wmma::mma_sync(c[f], af, bf, c[f]);
        }
    }

    // Convert to fp16 and store directly (out is padded past n).
    #pragma unroll
    for (int f = 0; f < 2; f++) {
        wmma::fragment<wmma::accumulator, 16, 16, 16, __half> ch;
        #pragma unroll
        for (int i = 0; i < ch.num_elements; i++)
            ch.x[i] = __float2half(c[f].x[i]);
        wmma::store_matrix_sync(out + (size_t)(m0 + wm * 16) * 64 + wn * 32 + f * 16,
                                ch, 64, wmma::mem_row_major);
    }
}

// ---------------------------- Layer-2 aggregation ---------------------------

__global__ __launch_bounds__(256)
void agg2_kernel(const __half* __restrict__ h,
                 const int* __restrict__ rowptr,
                 const int* __restrict__ colx,
                 const float* __restrict__ dis,
                 const float* __restrict__ bias,
                 float* __restrict__ out, int n) {
    int w = (int)((blockIdx.x * blockDim.x + threadIdx.x) >> 5);
    int lane = threadIdx.x & 31;
    if (w >= n) return;

    float2 acc;
    {
        unsigned u = __ldg((const unsigned*)(h + (size_t)w * 64) + lane);
        acc = __half22float2(*(__half2*)&u);
    }
    int j  = __ldg(&rowptr[w]);
    int j1 = __ldg(&rowptr[w + 1]);
    for (; j + 1 < j1; j += 2) {
        int sA = __ldg(&colx[j]);
        int sB = __ldg(&colx[j + 1]);
        unsigned uA = __ldg((const unsigned*)(h + (size_t)sA * 64) + lane);
        unsigned uB = __ldg((const unsigned*)(h + (size_t)sB * 64) + lane);
        float2 va = __half22float2(*(__half2*)&uA);
        float2 vb = __half22float2(*(__half2*)&uB);
        acc.x += va.x + vb.x;
        acc.y += va.y + vb.y;
    }
    if (j < j1) {
        int s = __ldg(&colx[j]);
        unsigned u = __ldg((const unsigned*)(h + (size_t)s * 64) + lane);
        float2 v = __half22float2(*(__half2*)&u);
        acc.x += v.x;
        acc.y += v.y;
    }
    float sc = dis[w];
    float2 bb = *(const float2*)(bias + lane * 2);
    *(float2*)(out + (size_t)w * 64 + lane * 2) =
        make_float2(fmaf(sc, acc.x, bb.x), fmaf(sc, acc.y, bb.y));
}

// ---------------------------- Launch ----------------------------------------

extern "C" void kernel_launch(void* const* d_in, const int* in_sizes, int n_in,
                              void* d_out, int out_size) {
    const int*   types = (const int*)d_in[0];
    const int*   ei    = (const int*)d_in[1];
    const float* emb   = (const float*)d_in[2];
    const float* W1    = (const float*)d_in[3];
    const float* b1    = (const float*)d_in[4];
    const float* W2    = (const float*)d_in[5];
    const float* b2    = (const float*)d_in[6];
    float* out = (float*)d_out;

    int n  = in_sizes[0];
    int e  = in_sizes[1] / 2;
    int nt = in_sizes[2] / 128;
    if (n > MAXN) n = MAXN;
    if (e > MAXE) e = MAXE;
    if (nt > MAXT) nt = MAXT;
    const int* src = ei;
    const int* dst = ei + e;

    int *cnt, *rowptr, *wptr, *colx, *partials;
    float *dis;
    __half *ht, *a1s, *w2h, *h2;
    cudaGetSymbolAddress((void**)&cnt,      g_cnt);
    cudaGetSymbolAddress((void**)&rowptr,   g_rowptr);
    cudaGetSymbolAddress((void**)&wptr,     g_wptr);
    cudaGetSymbolAddress((void**)&colx,     g_col);
    cudaGetSymbolAddress((void**)&partials, g_partials);
    cudaGetSymbolAddress((void**)&dis,      g_dis);
    cudaGetSymbolAddress((void**)&ht,       g_ht);
    cudaGetSymbolAddress((void**)&a1s,      g_a1s);
    cudaGetSymbolAddress((void**)&w2h,      g_w2h);
    cudaGetSymbolAddress((void**)&h2,       g_h2);

    int nb_e = (e + 255) / 256;
    int nb   = (n + SCAN_CHUNK - 1) / SCAN_CHUNK;

    gemm_type_kernel<<<(nt + 63) / 64, 256>>>(emb, W1, ht, nt);
    w2h_kernel<<<32, 256>>>(W2, w2h);

    cudaMemsetAsync(cnt, 0, (size_t)n * sizeof(int));
    count_kernel<<<nb_e, 256>>>(dst, e, cnt);
    blocksum_kernel<<<nb, 256>>>(cnt, partials, n);
    scan_apply_kernel<<<nb, 256>>>(cnt, partials, rowptr, wptr, dis, n, nb);
    fill_kernel<<<nb_e, 256>>>(src, dst, e, wptr, colx);

    int agg_blocks = (n + 7) / 8;

    agg1_fused_kernel<<<agg_blocks, 256>>>(ht, types, rowptr, colx, dis, b1, a1s, n);

    gemm2_tc_kernel<<<(n + 63) / 64, 256>>>(a1s, w2h, h2, n);
    agg2_kernel<<<agg_blocks, 256>>>(h2, rowptr, colx, dis, b2, out, n);
}